// round 2
// baseline (speedup 1.0000x reference)
#include <cuda_runtime.h>

#define NPTS 131072
#define KNBR 27
#define FIN  3
#define FOUT 32
#define BN_EPS 1e-5f

// Intermediate h[N,32] (stage1 output after BN+SiLU). Static device scratch
// (no allocation allowed in kernel_launch).
__device__ float g_h[NPTS * FOUT];

// ---------------- packed f32x2 helpers ----------------
__device__ __forceinline__ unsigned long long pack2(float x, float y) {
    unsigned long long r;
    asm("mov.b64 %0, {%1, %2};" : "=l"(r) : "f"(x), "f"(y));
    return r;
}
__device__ __forceinline__ void unpack2(unsigned long long p, float& x, float& y) {
    asm("mov.b64 {%0, %1}, %2;" : "=f"(x), "=f"(y) : "l"(p));
}
__device__ __forceinline__ void ffma2(unsigned long long& d,
                                      unsigned long long a,
                                      unsigned long long b) {
    asm("fma.rn.f32x2 %0, %1, %2, %0;" : "+l"(d) : "l"(a), "l"(b));
}

__device__ __forceinline__ float silu(float x) {
    return x / (1.0f + expf(-x));
}

// ---------------- stage 1: gather-GEMM (FIN=3 -> 32) + BN + SiLU ----------------
__global__ __launch_bounds__(256) void stage1_kernel(
    const float* __restrict__ x,      // [N,3]
    const int*   __restrict__ nbr,    // [N,27]
    const float* __restrict__ w1,     // [27,3,32]
    const float* __restrict__ gamma,
    const float* __restrict__ beta,
    const float* __restrict__ mean,
    const float* __restrict__ var)
{
    __shared__ unsigned long long w1s[KNBR * FIN * FOUT / 2];  // 1296 pairs
    __shared__ float scale_s[FOUT], shift_s[FOUT];

    {
        float* w1sf = reinterpret_cast<float*>(w1s);
        for (int i = threadIdx.x; i < KNBR * FIN * FOUT; i += 256) w1sf[i] = w1[i];
    }
    if (threadIdx.x < FOUT) {
        int o = threadIdx.x;
        float s = gamma[o] * rsqrtf(var[o] + BN_EPS);
        scale_s[o] = s;
        shift_s[o] = beta[o] - mean[o] * s;
    }
    __syncthreads();

    int n = blockIdx.x * 256 + threadIdx.x;
    if (n >= NPTS) return;

    unsigned long long acc[FOUT / 2];
#pragma unroll
    for (int p = 0; p < FOUT / 2; p++) acc[p] = 0ull;

    const int* nb = nbr + n * KNBR;
#pragma unroll 1
    for (int k = 0; k < KNBR; k++) {
        int idx = nb[k];
        const float* xr = x + idx * 3;
        float x0 = xr[0], x1 = xr[1], x2 = xr[2];
        unsigned long long xv0 = pack2(x0, x0);
        unsigned long long xv1 = pack2(x1, x1);
        unsigned long long xv2 = pack2(x2, x2);
        const unsigned long long* wk = w1s + k * (FIN * FOUT / 2);  // 48 pairs
#pragma unroll
        for (int p = 0; p < FOUT / 2; p++) ffma2(acc[p], xv0, wk[p]);
#pragma unroll
        for (int p = 0; p < FOUT / 2; p++) ffma2(acc[p], xv1, wk[16 + p]);
#pragma unroll
        for (int p = 0; p < FOUT / 2; p++) ffma2(acc[p], xv2, wk[32 + p]);
    }

    // BN + SiLU, store as float4s
    float hv[FOUT];
#pragma unroll
    for (int p = 0; p < FOUT / 2; p++) {
        float a, b;
        unpack2(acc[p], a, b);
        int o = 2 * p;
        hv[o]     = silu(a * scale_s[o]     + shift_s[o]);
        hv[o + 1] = silu(b * scale_s[o + 1] + shift_s[o + 1]);
    }
    float4* hp = reinterpret_cast<float4*>(g_h + n * FOUT);
#pragma unroll
    for (int i = 0; i < FOUT / 4; i++)
        hp[i] = reinterpret_cast<float4*>(hv)[i];
}

// ---------------- stage 2: gather-GEMM (32 -> 32) + MLP branch + fuse ----------------
__global__ __launch_bounds__(256, 2) void stage2_kernel(
    const float* __restrict__ zf,     // [N,3]
    const int*   __restrict__ nbr,    // [N,27]
    const float* __restrict__ w2,     // [27,32,32]
    const float* __restrict__ mlpw,   // [3,32]
    const float* __restrict__ mlpb,
    const float* __restrict__ mg,
    const float* __restrict__ mb,
    const float* __restrict__ mm,
    const float* __restrict__ mv,
    float* __restrict__ out,
    int copies)
{
    extern __shared__ unsigned long long w2s[];  // 13824 pairs = 110592 B
    __shared__ float mlpw_s[FIN * FOUT];
    __shared__ float mlpb_s[FOUT], msc_s[FOUT], msh_s[FOUT];

    {
        float4* dst = reinterpret_cast<float4*>(w2s);
        const float4* src = reinterpret_cast<const float4*>(w2);
        for (int i = threadIdx.x; i < KNBR * FOUT * FOUT / 4; i += 256) dst[i] = src[i];
    }
    for (int i = threadIdx.x; i < FIN * FOUT; i += 256) mlpw_s[i] = mlpw[i];
    if (threadIdx.x < FOUT) {
        int o = threadIdx.x;
        float s = mg[o] * rsqrtf(mv[o] + BN_EPS);
        msc_s[o] = s;
        msh_s[o] = mb[o] - mm[o] * s;
        mlpb_s[o] = mlpb[o];
    }
    __syncthreads();

    int n = blockIdx.x * 256 + threadIdx.x;
    if (n >= NPTS) return;

    unsigned long long acc[FOUT / 2];
#pragma unroll
    for (int p = 0; p < FOUT / 2; p++) acc[p] = 0ull;

    const int* nb = nbr + n * KNBR;
#pragma unroll 1
    for (int k = 0; k < KNBR; k++) {
        int idx = nb[k];
        const float4* hp = reinterpret_cast<const float4*>(g_h + idx * FOUT);
        float4 r[FOUT / 4];
#pragma unroll
        for (int i = 0; i < FOUT / 4; i++) r[i] = hp[i];
        const float* rv = reinterpret_cast<const float*>(r);

        const ulonglong2* wk =
            reinterpret_cast<const ulonglong2*>(w2s + k * (FOUT * FOUT / 2));
#pragma unroll
        for (int f = 0; f < FOUT; f++) {
            float hvf = rv[f];
            unsigned long long hv2 = pack2(hvf, hvf);
#pragma unroll
            for (int p = 0; p < 8; p++) {
                ulonglong2 w = wk[f * 8 + p];
                ffma2(acc[2 * p],     hv2, w.x);
                ffma2(acc[2 * p + 1], hv2, w.y);
            }
        }
    }

    // point branch: Linear -> BN -> ReLU
    const float* zr = zf + n * 3;
    float z0 = zr[0], z1 = zr[1], z2 = zr[2];
    float res[FOUT];
#pragma unroll
    for (int o = 0; o < FOUT; o++) {
        float zl = fmaf(z0, mlpw_s[o],
                   fmaf(z1, mlpw_s[FOUT + o],
                   fmaf(z2, mlpw_s[2 * FOUT + o], mlpb_s[o])));
        zl = fmaf(zl, msc_s[o], msh_s[o]);
        res[o] = fmaxf(zl, 0.0f);
    }
#pragma unroll
    for (int p = 0; p < FOUT / 2; p++) {
        float a, b;
        unpack2(acc[p], a, b);
        res[2 * p]     += a;
        res[2 * p + 1] += b;
    }

    float4* op = reinterpret_cast<float4*>(out + (size_t)n * FOUT);
#pragma unroll
    for (int i = 0; i < FOUT / 4; i++)
        op[i] = reinterpret_cast<float4*>(res)[i];
    if (copies > 1) {
        float4* op2 = reinterpret_cast<float4*>(out + (size_t)NPTS * FOUT + (size_t)n * FOUT);
#pragma unroll
        for (int i = 0; i < FOUT / 4; i++)
            op2[i] = reinterpret_cast<float4*>(res)[i];
    }
}

extern "C" void kernel_launch(void* const* d_in, const int* in_sizes, int n_in,
                              void* d_out, int out_size) {
    const float* x_feats   = (const float*)d_in[0];
    const float* z_feats   = (const float*)d_in[1];
    const int*   nbr_idx   = (const int*)  d_in[2];
    const float* w1        = (const float*)d_in[3];
    const float* bn1_gamma = (const float*)d_in[4];
    const float* bn1_beta  = (const float*)d_in[5];
    const float* bn1_mean  = (const float*)d_in[6];
    const float* bn1_var   = (const float*)d_in[7];
    const float* w2        = (const float*)d_in[8];
    const float* mlp_w     = (const float*)d_in[9];
    const float* mlp_b     = (const float*)d_in[10];
    const float* mlp_gamma = (const float*)d_in[11];
    const float* mlp_beta  = (const float*)d_in[12];
    const float* mlp_mean  = (const float*)d_in[13];
    const float* mlp_var   = (const float*)d_in[14];

    int N = in_sizes[0] / FIN;           // 131072
    int copies = out_size / (N * FOUT);  // expect 2 (tuple (fused, fused))

    const int smem2 = (KNBR * FOUT * FOUT / 2) * sizeof(unsigned long long);  // 110592
    cudaFuncSetAttribute(stage2_kernel,
                         cudaFuncAttributeMaxDynamicSharedMemorySize, smem2);

    int blocks = (N + 255) / 256;
    stage1_kernel<<<blocks, 256>>>(x_feats, nbr_idx, w1,
                                   bn1_gamma, bn1_beta, bn1_mean, bn1_var);
    stage2_kernel<<<blocks, 256, smem2>>>(z_feats, nbr_idx, w2,
                                          mlp_w, mlp_b, mlp_gamma, mlp_beta,
                                          mlp_mean, mlp_var,
                                          (float*)d_out, copies);
}

// round 3
// speedup vs baseline: 1.4598x; 1.4598x over previous
#include <cuda_runtime.h>
#include <cstdint>

#define NPTS 131072
#define KNBR 27
#define FIN  3
#define FOUT 32
#define BN_EPS 1e-5f

#define TILE_P  128
#define ASTRIDE 36   // padded row stride (floats) for conflict-free A frags

// Intermediate h[N,32] (stage1 output after BN+SiLU).
__device__ float g_h[NPTS * FOUT];

// ---------------- packed f32x2 helpers ----------------
__device__ __forceinline__ unsigned long long pack2(float x, float y) {
    unsigned long long r;
    asm("mov.b64 %0, {%1, %2};" : "=l"(r) : "f"(x), "f"(y));
    return r;
}
__device__ __forceinline__ void unpack2(unsigned long long p, float& x, float& y) {
    asm("mov.b64 {%0, %1}, %2;" : "=f"(x), "=f"(y) : "l"(p));
}
__device__ __forceinline__ void ffma2(unsigned long long& d,
                                      unsigned long long a,
                                      unsigned long long b) {
    asm("fma.rn.f32x2 %0, %1, %2, %0;" : "+l"(d) : "l"(a), "l"(b));
}

__device__ __forceinline__ void cp16(uint32_t smem_dst, const void* gmem_src) {
    asm volatile("cp.async.cg.shared.global [%0], [%1], 16;"
                 :: "r"(smem_dst), "l"(gmem_src) : "memory");
}
__device__ __forceinline__ void cp_commit() {
    asm volatile("cp.async.commit_group;" ::: "memory");
}
__device__ __forceinline__ void cp_wait_all() {
    asm volatile("cp.async.wait_group 0;" ::: "memory");
}

__device__ __forceinline__ float silu(float x) {
    return x / (1.0f + expf(-x));
}

// ---------------- stage 1: gather-GEMM (3 -> 32) + BN + SiLU ----------------
__global__ __launch_bounds__(256) void stage1_kernel(
    const float* __restrict__ x,      // [N,3]
    const int*   __restrict__ nbr,    // [N,27]
    const float* __restrict__ w1,     // [27,3,32]
    const float* __restrict__ gamma,
    const float* __restrict__ beta,
    const float* __restrict__ mean,
    const float* __restrict__ var)
{
    __shared__ unsigned long long w1s[KNBR * FIN * FOUT / 2];  // 1296 pairs
    __shared__ float scale_s[FOUT], shift_s[FOUT];

    {
        float* w1sf = reinterpret_cast<float*>(w1s);
        for (int i = threadIdx.x; i < KNBR * FIN * FOUT; i += 256) w1sf[i] = w1[i];
    }
    if (threadIdx.x < FOUT) {
        int o = threadIdx.x;
        float s = gamma[o] * rsqrtf(var[o] + BN_EPS);
        scale_s[o] = s;
        shift_s[o] = beta[o] - mean[o] * s;
    }
    __syncthreads();

    int n = blockIdx.x * 256 + threadIdx.x;
    if (n >= NPTS) return;

    unsigned long long acc[FOUT / 2];
#pragma unroll
    for (int p = 0; p < FOUT / 2; p++) acc[p] = 0ull;

    const int* nb = nbr + n * KNBR;
#pragma unroll 1
    for (int k3 = 0; k3 < KNBR / 3; k3++) {
        // batch the 3 index loads and 9 x loads for MLP
        int i0 = nb[3 * k3 + 0];
        int i1 = nb[3 * k3 + 1];
        int i2 = nb[3 * k3 + 2];
        const float* x0p = x + i0 * 3;
        const float* x1p = x + i1 * 3;
        const float* x2p = x + i2 * 3;
        float xv[9];
        xv[0] = x0p[0]; xv[1] = x0p[1]; xv[2] = x0p[2];
        xv[3] = x1p[0]; xv[4] = x1p[1]; xv[5] = x1p[2];
        xv[6] = x2p[0]; xv[7] = x2p[1]; xv[8] = x2p[2];
#pragma unroll
        for (int kk = 0; kk < 3; kk++) {
            int k = 3 * k3 + kk;
            const unsigned long long* wk = w1s + k * (FIN * FOUT / 2);
#pragma unroll
            for (int f = 0; f < 3; f++) {
                unsigned long long xv2 = pack2(xv[kk * 3 + f], xv[kk * 3 + f]);
#pragma unroll
                for (int p = 0; p < FOUT / 2; p++)
                    ffma2(acc[p], xv2, wk[f * 16 + p]);
            }
        }
    }

    float hv[FOUT];
#pragma unroll
    for (int p = 0; p < FOUT / 2; p++) {
        float a, b;
        unpack2(acc[p], a, b);
        int o = 2 * p;
        hv[o]     = silu(a * scale_s[o]     + shift_s[o]);
        hv[o + 1] = silu(b * scale_s[o + 1] + shift_s[o + 1]);
    }
    float4* hp = reinterpret_cast<float4*>(g_h + n * FOUT);
#pragma unroll
    for (int i = 0; i < FOUT / 4; i++)
        hp[i] = reinterpret_cast<float4*>(hv)[i];
}

// ---------------- stage 2: register-tiled gather-GEMM (32 -> 32) ----------------
// CTA: 128 threads, 128-point tile. Thread (og = tid%4, pg = tid/4) computes
// points {pg, pg+32, pg+64, pg+96} x outputs [og*8, og*8+8).
//
// dyn smem layout (float units):
//   A:   [2][128][ASTRIDE]       off 0      size 9216
//   B:   [2][32][32]             off 9216   size 2048
//   idx: [128*27] (int)          off 11264  size 3456
//   mlpw:[3][32]                 off 14720  size 96
//   mlpb/msc/msh: 32 each        off 14816/14848/14880
// total 14912 floats = 59648 B
#define S2_SMEM_FLOATS 14912

__global__ __launch_bounds__(128) void stage2_kernel(
    const float* __restrict__ zf,     // [N,3]
    const int*   __restrict__ nbr,    // [N,27]
    const float* __restrict__ w2,     // [27,32,32]
    const float* __restrict__ mlpw,   // [3,32]
    const float* __restrict__ mlpb,
    const float* __restrict__ mg,
    const float* __restrict__ mb,
    const float* __restrict__ mm,
    const float* __restrict__ mv,
    float* __restrict__ out,
    int copies)
{
    extern __shared__ float sm[];
    float* Asm    = sm;                            // [2][128][ASTRIDE]
    float* Bsm    = sm + 9216;                     // [2][32][32]
    int*   idxs   = reinterpret_cast<int*>(sm + 11264);  // [128*27]
    float* mlpw_s = sm + 14720;
    float* mlpb_s = sm + 14816;
    float* msc_s  = sm + 14848;
    float* msh_s  = sm + 14880;

    const int tid  = threadIdx.x;
    const int base = blockIdx.x * TILE_P;

    // preload neighbor indices for the whole tile (contiguous, coalesced)
    {
        const int* nbase = nbr + (size_t)base * KNBR;
        for (int i = tid; i < TILE_P * KNBR; i += 128) idxs[i] = nbase[i];
    }
    for (int i = tid; i < FIN * FOUT; i += 128) mlpw_s[i] = mlpw[i];
    if (tid < FOUT) {
        int o = tid;
        float s = mg[o] * rsqrtf(mv[o] + BN_EPS);
        msc_s[o] = s;
        msh_s[o] = mb[o] - mm[o] * s;
        mlpb_s[o] = mlpb[o];
    }
    __syncthreads();

    const uint32_t Asm_u32 = (uint32_t)__cvta_generic_to_shared(Asm);
    const uint32_t Bsm_u32 = (uint32_t)__cvta_generic_to_shared(Bsm);

    // issue async gather of k-slice into buffer (k&1)
    auto issue = [&](int k) {
        int buf = k & 1;
        int idx = idxs[tid * KNBR + k];
        const char* src = (const char*)(g_h + (size_t)idx * FOUT);
        uint32_t dst = Asm_u32 + (uint32_t)(buf * TILE_P * ASTRIDE + tid * ASTRIDE) * 4u;
#pragma unroll
        for (int c = 0; c < 8; c++) cp16(dst + c * 16, src + c * 16);
        // w2 slice: 4KB contiguous, 32B per thread
        const char* bsrc = (const char*)(w2 + (size_t)k * FOUT * FOUT) + tid * 32;
        uint32_t bdst = Bsm_u32 + (uint32_t)(buf * 1024) * 4u + tid * 32;
        cp16(bdst, bsrc);
        cp16(bdst + 16, bsrc + 16);
        cp_commit();
    };

    const int og = tid & 3;        // output group: outputs [og*8, og*8+8)
    const int pg = tid >> 2;       // point group:  points {pg + 32j}

    unsigned long long acc[16];
#pragma unroll
    for (int i = 0; i < 16; i++) acc[i] = 0ull;

    issue(0);

#pragma unroll 1
    for (int k = 0; k < KNBR; k++) {
        cp_wait_all();
        __syncthreads();          // k's data visible; all warps done with k-1
        if (k + 1 < KNBR) issue(k + 1);   // overlaps with compute(k)

        const float* A = Asm + (k & 1) * TILE_P * ASTRIDE;
        const float* B = Bsm + (k & 1) * 1024;

#pragma unroll
        for (int fc = 0; fc < 8; fc++) {
            float a[4][4];
            *reinterpret_cast<float4*>(a[0]) =
                *reinterpret_cast<const float4*>(A + (pg     ) * ASTRIDE + fc * 4);
            *reinterpret_cast<float4*>(a[1]) =
                *reinterpret_cast<const float4*>(A + (pg + 32) * ASTRIDE + fc * 4);
            *reinterpret_cast<float4*>(a[2]) =
                *reinterpret_cast<const float4*>(A + (pg + 64) * ASTRIDE + fc * 4);
            *reinterpret_cast<float4*>(a[3]) =
                *reinterpret_cast<const float4*>(A + (pg + 96) * ASTRIDE + fc * 4);
#pragma unroll
            for (int f = 0; f < 4; f++) {
                const ulonglong2* bp = reinterpret_cast<const ulonglong2*>(
                    B + (fc * 4 + f) * FOUT + og * 8);
                ulonglong2 b0 = bp[0];   // outputs og*8 + 0..3
                ulonglong2 b1 = bp[1];   // outputs og*8 + 4..7
#pragma unroll
                for (int j = 0; j < 4; j++) {
                    unsigned long long av2 = pack2(a[j][f], a[j][f]);
                    ffma2(acc[j * 4 + 0], av2, b0.x);
                    ffma2(acc[j * 4 + 1], av2, b0.y);
                    ffma2(acc[j * 4 + 2], av2, b1.x);
                    ffma2(acc[j * 4 + 3], av2, b1.y);
                }
            }
        }
    }

    // epilogue: point branch + fuse + store (both output copies)
#pragma unroll
    for (int j = 0; j < 4; j++) {
        int p = base + pg + 32 * j;
        const float* zr = zf + (size_t)p * 3;
        float z0 = zr[0], z1 = zr[1], z2 = zr[2];
        float res[8];
#pragma unroll
        for (int i = 0; i < 8; i++) {
            int o = og * 8 + i;
            float zl = fmaf(z0, mlpw_s[o],
                       fmaf(z1, mlpw_s[FOUT + o],
                       fmaf(z2, mlpw_s[2 * FOUT + o], mlpb_s[o])));
            zl = fmaf(zl, msc_s[o], msh_s[o]);
            res[i] = fmaxf(zl, 0.0f);
        }
#pragma unroll
        for (int q = 0; q < 4; q++) {
            float a, b;
            unpack2(acc[j * 4 + q], a, b);
            res[2 * q]     += a;
            res[2 * q + 1] += b;
        }
        float4* op = reinterpret_cast<float4*>(out + (size_t)p * FOUT + og * 8);
        op[0] = reinterpret_cast<float4*>(res)[0];
        op[1] = reinterpret_cast<float4*>(res)[1];
        if (copies > 1) {
            float4* op2 = reinterpret_cast<float4*>(
                out + (size_t)NPTS * FOUT + (size_t)p * FOUT + og * 8);
            op2[0] = reinterpret_cast<float4*>(res)[0];
            op2[1] = reinterpret_cast<float4*>(res)[1];
        }
    }
}

extern "C" void kernel_launch(void* const* d_in, const int* in_sizes, int n_in,
                              void* d_out, int out_size) {
    const float* x_feats   = (const float*)d_in[0];
    const float* z_feats   = (const float*)d_in[1];
    const int*   nbr_idx   = (const int*)  d_in[2];
    const float* w1        = (const float*)d_in[3];
    const float* bn1_gamma = (const float*)d_in[4];
    const float* bn1_beta  = (const float*)d_in[5];
    const float* bn1_mean  = (const float*)d_in[6];
    const float* bn1_var   = (const float*)d_in[7];
    const float* w2        = (const float*)d_in[8];
    const float* mlp_w     = (const float*)d_in[9];
    const float* mlp_b     = (const float*)d_in[10];
    const float* mlp_gamma = (const float*)d_in[11];
    const float* mlp_beta  = (const float*)d_in[12];
    const float* mlp_mean  = (const float*)d_in[13];
    const float* mlp_var   = (const float*)d_in[14];

    int N = in_sizes[0] / FIN;           // 131072
    int copies = out_size / (N * FOUT);  // 2

    const int smem2 = S2_SMEM_FLOATS * sizeof(float);  // 59648 B
    cudaFuncSetAttribute(stage2_kernel,
                         cudaFuncAttributeMaxDynamicSharedMemorySize, smem2);

    stage1_kernel<<<(N + 255) / 256, 256>>>(x_feats, nbr_idx, w1,
                                            bn1_gamma, bn1_beta, bn1_mean, bn1_var);
    stage2_kernel<<<N / TILE_P, 128, smem2>>>(z_feats, nbr_idx, w2,
                                              mlp_w, mlp_b, mlp_gamma, mlp_beta,
                                              mlp_mean, mlp_var,
                                              (float*)d_out, copies);
}